// round 3
// baseline (speedup 1.0000x reference)
#include <cuda_runtime.h>

// Problem constants
#define BI 4
#define SS 1024
#define DM 1024
#define NH 16
#define DH 64
#define MROWS (BI * SS)            // 4096
#define OUT_ELEMS (MROWS * DM)     // 4194304

// Scratch (device globals; allocation inside kernel_launch is forbidden)
__device__ float g_q[MROWS * DM];
__device__ float g_k[MROWS * DM];
__device__ float g_v[MROWS * DM];
__device__ float g_ctx[MROWS * DM];
__device__ float g_y[MROWS * DM];
__device__ int   g_mask_is_int32;

// ---------------------------------------------------------------------------
// tf32 helpers
// ---------------------------------------------------------------------------
__device__ __forceinline__ unsigned f2tf(float x) {
    unsigned u;
    asm("cvt.rna.tf32.f32 %0, %1;" : "=r"(u) : "f"(x));
    return u;
}
__device__ __forceinline__ uint4 tf32x4(float4 v) {
    uint4 t;
    t.x = f2tf(v.x); t.y = f2tf(v.y); t.z = f2tf(v.z); t.w = f2tf(v.w);
    return t;
}

#define MMA_TF32(d, a, b0, b1) \
    asm volatile("mma.sync.aligned.m16n8k8.row.col.f32.tf32.tf32.f32 " \
                 "{%0,%1,%2,%3}, {%4,%5,%6,%7}, {%8,%9}, {%0,%1,%2,%3};" \
                 : "+f"(d[0]), "+f"(d[1]), "+f"(d[2]), "+f"(d[3]) \
                 : "r"(a[0]), "r"(a[1]), "r"(a[2]), "r"(a[3]), "r"(b0), "r"(b1))

// ---------------------------------------------------------------------------
// Mask dtype detection: int32 (values 0/1) vs uint8 bytes.
// ---------------------------------------------------------------------------
__global__ void detect_mask_kernel(const unsigned* m) {
    int ok = 1;
    for (int i = threadIdx.x; i < 1024; i += 32)
        if (m[i] > 1u) ok = 0;
    unsigned b = __ballot_sync(0xffffffffu, ok);
    if (threadIdx.x == 0) g_mask_is_int32 = (b == 0xffffffffu) ? 1 : 0;
}

// ---------------------------------------------------------------------------
// tf32 MMA tile body for the projection GEMMs (unchanged from R2).
// Block = BM x BN (BM=128), 256 threads = 8 warps (4m x 2n).
// ---------------------------------------------------------------------------
template<int BM, int BN, bool BNT>
__device__ __forceinline__ void mma_tile(
    const float* __restrict__ A, int lda,
    const float* __restrict__ B, int ldb,
    int K,
    float* __restrict__ As, float* __restrict__ Bs,
    float (&acc)[2][BN / 16][4])
{
    constexpr int NF = BN / 16;
    const int tid  = threadIdx.x;
    const int lane = tid & 31;
    const int wid  = tid >> 5;
    const int wm   = (wid & 3) * 32;
    const int wn   = (wid >> 2) * (BN / 2);
    const int r    = lane >> 2;
    const int cq   = lane & 3;

    unsigned* Asu = (unsigned*)As;
    unsigned* Bsu = (unsigned*)Bs;

    for (int k0 = 0; k0 < K; k0 += 16) {
        #pragma unroll
        for (int f = tid; f < BM * 4; f += 256) {
            int m = f >> 2, k4 = (f & 3) << 2;
            float4 v = *(const float4*)(A + (size_t)m * lda + k0 + k4);
            *(uint4*)(Asu + m * 20 + k4) = tf32x4(v);
        }
        if (BNT) {
            #pragma unroll
            for (int f = tid; f < BN * 4; f += 256) {
                int n = f >> 2, k4 = (f & 3) << 2;
                float4 v = *(const float4*)(B + (size_t)n * ldb + k0 + k4);
                *(uint4*)(Bsu + n * 20 + k4) = tf32x4(v);
            }
        } else {
            #pragma unroll
            for (int f = tid; f < BN * 4; f += 256) {
                int k = f & 15, n4 = f >> 4;
                float4 v = *(const float4*)(B + (size_t)(k0 + k) * ldb + 4 * n4);
                uint4 t = tf32x4(v);
                Bsu[(4 * n4 + 0) * 20 + k] = t.x;
                Bsu[(4 * n4 + 1) * 20 + k] = t.y;
                Bsu[(4 * n4 + 2) * 20 + k] = t.z;
                Bsu[(4 * n4 + 3) * 20 + k] = t.w;
            }
        }
        __syncthreads();

        #pragma unroll
        for (int ks = 0; ks < 2; ks++) {
            const int c = ks * 8 + cq;
            unsigned a[2][4];
            #pragma unroll
            for (int mf = 0; mf < 2; mf++) {
                const unsigned* p = Asu + (wm + mf * 16 + r) * 20 + c;
                a[mf][0] = p[0];
                a[mf][1] = p[8 * 20];
                a[mf][2] = p[4];
                a[mf][3] = p[8 * 20 + 4];
            }
            #pragma unroll
            for (int nf = 0; nf < NF; nf++) {
                const unsigned* p = Bsu + (wn + nf * 8 + r) * 20 + c;
                unsigned b0 = p[0], b1 = p[4];
                #pragma unroll
                for (int mf = 0; mf < 2; mf++) {
                    MMA_TF32(acc[mf][nf], a[mf], b0, b1);
                }
            }
        }
        __syncthreads();
    }
}

// ---------------------------------------------------------------------------
// 1) Fused QKV projections (NN): M=4096, N=1024, K=1024. Grid (8, 32, 3).
// ---------------------------------------------------------------------------
__global__ __launch_bounds__(256) void qkv_gemm_kernel(
    const float* __restrict__ Qin, const float* __restrict__ Kin, const float* __restrict__ Vin,
    const float* __restrict__ Wq, const float* __restrict__ Wk, const float* __restrict__ Wv,
    const float* __restrict__ bq, const float* __restrict__ bk, const float* __restrict__ bv)
{
    __shared__ float As[128 * 20];
    __shared__ float Bs[128 * 20];
    const float* A; const float* W; const float* bias; float* C;
    if (blockIdx.z == 0)      { A = Qin; W = Wq; bias = bq; C = g_q; }
    else if (blockIdx.z == 1) { A = Kin; W = Wk; bias = bk; C = g_k; }
    else                      { A = Vin; W = Wv; bias = bv; C = g_v; }
    const int bm = blockIdx.y * 128, bn = blockIdx.x * 128;
    float acc[2][8][4] = {};
    mma_tile<128, 128, false>(A + (size_t)bm * DM, DM, W + bn, DM, DM, As, Bs, acc);

    const int lane = threadIdx.x & 31, wid = threadIdx.x >> 5;
    const int wm = (wid & 3) * 32, wn = (wid >> 2) * 64;
    const int r = lane >> 2, cq = lane & 3;
    #pragma unroll
    for (int mf = 0; mf < 2; mf++) {
        #pragma unroll
        for (int nf = 0; nf < 8; nf++) {
            int row = bm + wm + mf * 16 + r;
            int col = bn + wn + nf * 8 + 2 * cq;
            float2 bia = *(const float2*)&bias[col];
            *(float2*)&C[(size_t)row * DM + col] =
                make_float2(acc[mf][nf][0] + bia.x, acc[mf][nf][1] + bia.y);
            *(float2*)&C[(size_t)(row + 8) * DM + col] =
                make_float2(acc[mf][nf][2] + bia.x, acc[mf][nf][3] + bia.y);
        }
    }
}

// ---------------------------------------------------------------------------
// 2) FUSED attention: scores + mask + softmax + attn-store + P@V.
// Block = 32 query rows of one (b,h). Grid (32, 64), 256 threads, 8 warps.
// The full 32x1024 score block lives in smem (stride 1028 floats: mma A-frag
// loads conflict-free since (4r+c)%32 distinct). Exact two-sweep softmax.
// ---------------------------------------------------------------------------
#define SS_STRIDE 1028
#define FUSED_SMEM_FLOATS (32 * SS_STRIDE + 32 * 68 + 8704 + 32)

__global__ __launch_bounds__(256) void fused_attn_kernel(
    const void* __restrict__ mask, float* __restrict__ attn_ext, int use_ext)
{
    extern __shared__ float smf[];
    float* Ss    = smf;                       // [32][1028] scores / P
    float* Qs    = Ss + 32 * SS_STRIDE;       // [32][68] tf32 Q tile
    float* KVs   = Qs + 32 * 68;              // K: [128][68] | V^T: [64][133]
    float* rstat = KVs + 8704;                // [32] rowmax then 1/rowsum
    unsigned* Ssu = (unsigned*)Ss;
    unsigned* Qsu = (unsigned*)Qs;
    unsigned* KVu = (unsigned*)KVs;

    const int tid = threadIdx.x, lane = tid & 31, wid = tid >> 5;
    const int r = lane >> 2, cq = lane & 3;
    const int bh = blockIdx.y, b = bh >> 4, h = bh & 15;
    const int i0 = blockIdx.x * 32;
    const float* qb = g_q + (size_t)b * SS * DM + h * DH;
    const float* kb = g_k + (size_t)b * SS * DM + h * DH;
    const float* vb = g_v + (size_t)b * SS * DM + h * DH;

    // Load Q tile (rows i0..i0+31, 64 cols) as tf32
    for (int f = tid; f < 32 * 16; f += 256) {
        int m = f >> 4, k4 = (f & 15) << 2;
        float4 v = *(const float4*)(qb + (size_t)(i0 + m) * DM + k4);
        *(uint4*)(Qsu + m * 68 + k4) = tf32x4(v);
    }

    // --- Phase 1: scores S = Q @ K^T into smem (raw, unscaled) ---
    {
        const int wm = (wid & 1) * 16, wn = (wid >> 1) * 32;
        for (int jt = 0; jt < 8; jt++) {
            __syncthreads();
            for (int f = tid; f < 128 * 16; f += 256) {
                int n = f >> 4, k4 = (f & 15) << 2;
                float4 v = *(const float4*)(kb + (size_t)(jt * 128 + n) * DM + k4);
                *(uint4*)(KVu + n * 68 + k4) = tf32x4(v);
            }
            __syncthreads();
            float acc[4][4] = {};
            #pragma unroll
            for (int kc = 0; kc < 8; kc++) {
                const int c = kc * 8 + cq;
                unsigned a[4];
                const unsigned* pa = Qsu + (wm + r) * 68 + c;
                a[0] = pa[0]; a[1] = pa[8 * 68]; a[2] = pa[4]; a[3] = pa[8 * 68 + 4];
                #pragma unroll
                for (int nf = 0; nf < 4; nf++) {
                    const unsigned* pb = KVu + (wn + nf * 8 + r) * 68 + c;
                    MMA_TF32(acc[nf], a, pb[0], pb[4]);
                }
            }
            #pragma unroll
            for (int nf = 0; nf < 4; nf++) {
                int col = jt * 128 + wn + nf * 8 + 2 * cq;
                *(float2*)&Ss[(wm + r) * SS_STRIDE + col] =
                    make_float2(acc[nf][0], acc[nf][1]);
                *(float2*)&Ss[(wm + r + 8) * SS_STRIDE + col] =
                    make_float2(acc[nf][2], acc[nf][3]);
            }
        }
    }
    __syncthreads();

    // --- Phase 2: mask + scale + rowmax (warp w owns rows 4w..4w+3) ---
    const int mi32 = g_mask_is_int32;
    const int* m32 = (const int*)mask;
    const unsigned char* m8 = (const unsigned char*)mask;
    #pragma unroll
    for (int rl = 0; rl < 4; rl++) {
        int row = wid * 4 + rl;
        size_t mbase = (size_t)b * SS * SS + (size_t)(i0 + row) * SS;
        float mx = -3.4e38f;
        #pragma unroll
        for (int it = 0; it < 8; it++) {
            int c0 = (it * 32 + lane) * 4;
            float4 s4 = *(float4*)&Ss[row * SS_STRIDE + c0];
            int mk0, mk1, mk2, mk3;
            if (mi32) {
                int4 mk = *(const int4*)(m32 + mbase + c0);
                mk0 = mk.x; mk1 = mk.y; mk2 = mk.z; mk3 = mk.w;
            } else {
                uchar4 u = *(const uchar4*)(m8 + mbase + c0);
                mk0 = u.x; mk1 = u.y; mk2 = u.z; mk3 = u.w;
            }
            s4.x = mk0 ? -1e9f : s4.x * 0.125f;
            s4.y = mk1 ? -1e9f : s4.y * 0.125f;
            s4.z = mk2 ? -1e9f : s4.z * 0.125f;
            s4.w = mk3 ? -1e9f : s4.w * 0.125f;
            *(float4*)&Ss[row * SS_STRIDE + c0] = s4;
            mx = fmaxf(mx, fmaxf(fmaxf(s4.x, s4.y), fmaxf(s4.z, s4.w)));
        }
        #pragma unroll
        for (int o = 16; o; o >>= 1) mx = fmaxf(mx, __shfl_xor_sync(0xffffffffu, mx, o));
        if (lane == 0) rstat[row] = mx;

        // --- Phase 3 (same row, no cross-warp dep): exp + rowsum ---
        float M = __shfl_sync(0xffffffffu, mx, 0);
        float s = 0.f;
        #pragma unroll
        for (int it = 0; it < 8; it++) {
            int c0 = (it * 32 + lane) * 4;
            float4 v = *(float4*)&Ss[row * SS_STRIDE + c0];
            v.x = __expf(v.x - M); v.y = __expf(v.y - M);
            v.z = __expf(v.z - M); v.w = __expf(v.w - M);
            *(float4*)&Ss[row * SS_STRIDE + c0] = v;
            s += v.x + v.y + v.z + v.w;
        }
        #pragma unroll
        for (int o = 16; o; o >>= 1) s += __shfl_xor_sync(0xffffffffu, s, o);
        float inv = 1.0f / s;

        // --- Phase 4: normalize, optional attn store, cvt to tf32 in smem ---
        size_t abase = (size_t)bh * SS * SS + (size_t)(i0 + row) * SS;
        #pragma unroll
        for (int it = 0; it < 8; it++) {
            int c0 = (it * 32 + lane) * 4;
            float4 v = *(float4*)&Ss[row * SS_STRIDE + c0];
            v.x *= inv; v.y *= inv; v.z *= inv; v.w *= inv;
            if (use_ext) *(float4*)&attn_ext[abase + c0] = v;
            *(uint4*)(Ssu + row * SS_STRIDE + c0) = tf32x4(v);
        }
    }

    // --- Phase 5: ctx = P @ V ---
    const int wm2 = (wid & 1) * 16, wn2 = (wid >> 1) * 16;
    float acc[2][4] = {};
    for (int kt = 0; kt < 8; kt++) {
        __syncthreads();   // prior mma reads done / phase-4 Ss writes visible
        for (int f = tid; f < 128 * 16; f += 256) {
            int s_ = f >> 4, n4 = (f & 15) << 2;
            float4 v = *(const float4*)(vb + (size_t)(kt * 128 + s_) * DM + n4);
            uint4 t = tf32x4(v);
            KVu[(n4 + 0) * 133 + s_] = t.x;
            KVu[(n4 + 1) * 133 + s_] = t.y;
            KVu[(n4 + 2) * 133 + s_] = t.z;
            KVu[(n4 + 3) * 133 + s_] = t.w;
        }
        __syncthreads();
        #pragma unroll
        for (int kc = 0; kc < 16; kc++) {
            const int ck = kc * 8 + cq;
            unsigned a[4];
            const unsigned* pa = Ssu + (wm2 + r) * SS_STRIDE + kt * 128 + ck;
            a[0] = pa[0]; a[1] = pa[8 * SS_STRIDE]; a[2] = pa[4]; a[3] = pa[8 * SS_STRIDE + 4];
            #pragma unroll
            for (int nf = 0; nf < 2; nf++) {
                const unsigned* pb = KVu + (wn2 + nf * 8 + r) * 133 + ck;
                MMA_TF32(acc[nf], a, pb[0], pb[4]);
            }
        }
    }
    float* cb = g_ctx + (size_t)b * SS * DM + h * DH;
    #pragma unroll
    for (int nf = 0; nf < 2; nf++) {
        int row = i0 + wm2 + r;
        int col = wn2 + nf * 8 + 2 * cq;
        *(float2*)&cb[(size_t)row * DM + col] = make_float2(acc[nf][0], acc[nf][1]);
        *(float2*)&cb[(size_t)(row + 8) * DM + col] = make_float2(acc[nf][2], acc[nf][3]);
    }
}

// ---------------------------------------------------------------------------
// 3) Output projection + residual (NN): y = ctx @ Wo + bo + Qin. Grid (8, 32).
// ---------------------------------------------------------------------------
__global__ __launch_bounds__(256) void outproj_kernel(
    const float* __restrict__ Wo, const float* __restrict__ bo,
    const float* __restrict__ Qres)
{
    __shared__ float As[128 * 20];
    __shared__ float Bs[128 * 20];
    const int bm = blockIdx.y * 128, bn = blockIdx.x * 128;
    float acc[2][8][4] = {};
    mma_tile<128, 128, false>(g_ctx + (size_t)bm * DM, DM, Wo + bn, DM, DM, As, Bs, acc);

    const int lane = threadIdx.x & 31, wid = threadIdx.x >> 5;
    const int wm = (wid & 3) * 32, wn = (wid >> 2) * 64;
    const int r = lane >> 2, cq = lane & 3;
    #pragma unroll
    for (int mf = 0; mf < 2; mf++) {
        #pragma unroll
        for (int nf = 0; nf < 8; nf++) {
            int row = bm + wm + mf * 16 + r;
            int col = bn + wn + nf * 8 + 2 * cq;
            float2 bia = *(const float2*)&bo[col];
            float2 q0 = *(const float2*)&Qres[(size_t)row * DM + col];
            float2 q1 = *(const float2*)&Qres[(size_t)(row + 8) * DM + col];
            *(float2*)&g_y[(size_t)row * DM + col] =
                make_float2(acc[mf][nf][0] + bia.x + q0.x, acc[mf][nf][1] + bia.y + q0.y);
            *(float2*)&g_y[(size_t)(row + 8) * DM + col] =
                make_float2(acc[mf][nf][2] + bia.x + q1.x, acc[mf][nf][3] + bia.y + q1.y);
        }
    }
}

// ---------------------------------------------------------------------------
// 4) LayerNorm over last dim (1024), biased variance, eps 1e-5. Grid 4096x256.
// ---------------------------------------------------------------------------
__global__ __launch_bounds__(256) void ln_kernel(
    const float* __restrict__ gamma, const float* __restrict__ beta,
    float* __restrict__ out)
{
    const float4* row = (const float4*)(g_y + (size_t)blockIdx.x * DM);
    const int t = threadIdx.x, lane = t & 31, w = t >> 5;
    __shared__ float s1[8], s2[8];
    float4 x = row[t];
    float a = x.x + x.y + x.z + x.w;
    float b = x.x * x.x + x.y * x.y + x.z * x.z + x.w * x.w;
    #pragma unroll
    for (int o = 16; o > 0; o >>= 1) {
        a += __shfl_xor_sync(0xffffffffu, a, o);
        b += __shfl_xor_sync(0xffffffffu, b, o);
    }
    if (lane == 0) { s1[w] = a; s2[w] = b; }
    __syncthreads();
    float A = 0.f, B2 = 0.f;
    #pragma unroll
    for (int i = 0; i < 8; i++) { A += s1[i]; B2 += s2[i]; }
    float mean = A * (1.0f / 1024.0f);
    float var = B2 * (1.0f / 1024.0f) - mean * mean;
    float rstd = rsqrtf(var + 1e-5f);
    float4 g = ((const float4*)gamma)[t];
    float4 be = ((const float4*)beta)[t];
    float4 o4;
    o4.x = (x.x - mean) * rstd * g.x + be.x;
    o4.y = (x.y - mean) * rstd * g.y + be.y;
    o4.z = (x.z - mean) * rstd * g.z + be.z;
    o4.w = (x.w - mean) * rstd * g.w + be.w;
    ((float4*)(out + (size_t)blockIdx.x * DM))[t] = o4;
}

// ---------------------------------------------------------------------------
extern "C" void kernel_launch(void* const* d_in, const int* in_sizes, int n_in,
                              void* d_out, int out_size) {
    const float* Qin   = (const float*)d_in[0];
    const float* Kin   = (const float*)d_in[1];
    const float* Vin   = (const float*)d_in[2];
    const void*  mask  = d_in[3];
    const float* Wq    = (const float*)d_in[4];
    const float* bq    = (const float*)d_in[5];
    const float* Wk    = (const float*)d_in[6];
    const float* bk    = (const float*)d_in[7];
    const float* Wv    = (const float*)d_in[8];
    const float* bv    = (const float*)d_in[9];
    const float* Wo    = (const float*)d_in[10];
    const float* bo    = (const float*)d_in[11];
    const float* gamma = (const float*)d_in[12];
    const float* beta  = (const float*)d_in[13];
    float* out = (float*)d_out;

    const int use_ext = (out_size > OUT_ELEMS) ? 1 : 0;
    float* attn_ext = out + OUT_ELEMS;

    const int fused_smem = FUSED_SMEM_FLOATS * 4;   // 175232 bytes
    cudaFuncSetAttribute(fused_attn_kernel,
                         cudaFuncAttributeMaxDynamicSharedMemorySize, fused_smem);

    detect_mask_kernel<<<1, 32>>>((const unsigned*)mask);
    qkv_gemm_kernel<<<dim3(8, 32, 3), 256>>>(Qin, Kin, Vin, Wq, Wk, Wv, bq, bk, bv);
    fused_attn_kernel<<<dim3(32, 64), 256, fused_smem>>>(mask, attn_ext, use_ext);
    outproj_kernel<<<dim3(8, 32), 256>>>(Wo, bo, Qin);
    ln_kernel<<<dim3(MROWS), 256>>>(gamma, beta, out);
    (void)in_sizes; (void)n_in;
}